// round 1
// baseline (speedup 1.0000x reference)
#include <cuda_runtime.h>

// YOLOv1 loss, fused single pass.
// pred/target: [4096, 7, 7, 90] float32, contiguous. Output: scalar float32.
//
// One warp per grid cell. Lane l loads elements l, l+32, (l<26 ? l+64).
// Class loss (idx 10..89) reduced across the warp; box/conf math (idx 0..9)
// done by lane 0 after shfl broadcast. Persistent grid -> few atomics.

#define NFEAT 90
#define NCELLS (4096 * 7 * 7)   // 200704
#define INV_BATCH (1.0f / 4096.0f)

__global__ void yolo_zero_kernel(float* out) {
    if (threadIdx.x == 0) out[0] = 0.0f;
}

__global__ __launch_bounds__(256) void yolo_loss_kernel(
    const float* __restrict__ pred,
    const float* __restrict__ target,
    float* __restrict__ out)
{
    const float inv_s = 1.0f / 7.0f;
    const unsigned FULL = 0xffffffffu;

    const int lane    = threadIdx.x & 31;
    const int warp_g  = (blockIdx.x * blockDim.x + threadIdx.x) >> 5;
    const int nwarps  = (gridDim.x * blockDim.x) >> 5;

    float acc = 0.0f;

    for (int c = warp_g; c < NCELLS; c += nwarps) {
        const float* p = pred   + (size_t)c * NFEAT;
        const float* t = target + (size_t)c * NFEAT;

        // Front-batched coalesced loads (MLP = 6)
        float p0 = p[lane];
        float t0 = t[lane];
        float p1 = p[lane + 32];
        float t1 = t[lane + 32];
        float p2 = 0.0f, t2 = 0.0f;
        if (lane < 26) { p2 = p[lane + 64]; t2 = t[lane + 64]; }

        // ---- class loss partial: indices 10..89 ----
        float d1 = p1 - t1;           // idx 32..63, all class
        float d2 = p2 - t2;           // idx 64..89 (masked by load=0 diff=0)
        float cls = d1 * d1 + d2 * d2;
        if (lane >= 10) {             // idx 10..31
            float d0 = p0 - t0;
            cls += d0 * d0;
        }
        #pragma unroll
        for (int o = 16; o > 0; o >>= 1)
            cls += __shfl_xor_sync(FULL, cls, o);

        // ---- broadcast first 10 elements of each tensor ----
        float pp[10], tt[10];
        #pragma unroll
        for (int k = 0; k < 10; k++) {
            pp[k] = __shfl_sync(FULL, p0, k);
            tt[k] = __shfl_sync(FULL, t0, k);
        }

        if (lane == 0) {
            float conf_t  = tt[4];
            float coord_m = (conf_t > 0.0f)  ? 1.0f : 0.0f;
            float noobj_m = (conf_t == 0.0f) ? 1.0f : 0.0f;

            // no-object confidence loss (conf cols 4 and 9)
            float d4 = pp[4] - tt[4];
            float d9 = pp[9] - tt[9];
            float noobj = noobj_m * (d4 * d4 + d9 * d9);

            // pred boxes b = 0,1 : elements [5b..5b+4]
            float pax[2], pay[2], pbx[2], pby[2];
            #pragma unroll
            for (int b = 0; b < 2; b++) {
                float x = pp[5 * b + 0], y = pp[5 * b + 1];
                float w = pp[5 * b + 2], h = pp[5 * b + 3];
                pax[b] = x * inv_s - 0.5f * w;
                pay[b] = y * inv_s - 0.5f * h;
                pbx[b] = pax[b] * inv_s + 0.5f * w;
                pby[b] = pay[b] * inv_s + 0.5f * h;
            }

            // target box 0
            float tx = tt[0], ty = tt[1], tw = tt[2], th = tt[3];
            float tax = tx * inv_s - 0.5f * tw;
            float tay = ty * inv_s - 0.5f * th;
            float tbx = tax * inv_s + 0.5f * tw;
            float tby = tay * inv_s + 0.5f * th;
            float t_area = (tbx - tax) * (tby - tay);

            float iou[2];
            #pragma unroll
            for (int b = 0; b < 2; b++) {
                float tlx = fmaxf(pax[b], tax);
                float tly = fmaxf(pay[b], tay);
                float brx = fminf(pbx[b], tbx);
                float bry = fminf(pby[b], tby);
                float w  = fmaxf(brx - tlx, 0.0f);
                float h  = fmaxf(bry - tly, 0.0f);
                float inter  = w * h;
                float p_area = (pbx[b] - pax[b]) * (pby[b] - pay[b]);
                iou[b] = inter / (p_area + t_area - inter);
            }

            // argmax (first max on tie -> strict >)
            int   idx     = (iou[1] > iou[0]) ? 1 : 0;
            float max_iou = iou[idx];

            // psel = [pa, pb2, pred_conf] of selected box
            float psx = pax[idx], psy = pay[idx];
            float psw = pbx[idx], psh = pby[idx];
            float psc = pp[5 * idx + 4];

            // tsel: transformed first box if idx==0 else raw second box
            float tsx, tsy, tsw, tsh;
            if (idx == 0) { tsx = tax;   tsy = tay;   tsw = tbx;   tsh = tby; }
            else          { tsx = tt[5]; tsy = tt[6]; tsw = tt[7]; tsh = tt[8]; }

            float dx = psx - tsx, dy = psy - tsy;
            float dw = psw - tsw, dh = psh - tsh;
            float xy_wh = dx * dx + dy * dy + dw * dw + dh * dh;

            float dc = psc - max_iou;

            float cell = coord_m * (5.0f * xy_wh + dc * dc + cls)
                       + 0.5f * noobj;
            acc += cell;
        }
    }

    // block reduction over warp leaders
    __shared__ float smem[8];
    if (lane == 0) smem[threadIdx.x >> 5] = acc;
    __syncthreads();
    if (threadIdx.x == 0) {
        float tot = 0.0f;
        #pragma unroll
        for (int i = 0; i < 8; i++) tot += smem[i];
        atomicAdd(out, tot * INV_BATCH);
    }
}

extern "C" void kernel_launch(void* const* d_in, const int* in_sizes, int n_in,
                              void* d_out, int out_size) {
    const float* pred   = (const float*)d_in[0];
    const float* target = (const float*)d_in[1];
    float* out = (float*)d_out;
    (void)in_sizes; (void)n_in; (void)out_size;

    yolo_zero_kernel<<<1, 32>>>(out);
    // 1184 blocks = 8 per SM on 148 SMs, 256 threads (8 warps) each.
    yolo_loss_kernel<<<1184, 256>>>(pred, target, out);
}

// round 2
// speedup vs baseline: 1.6964x; 1.6964x over previous
#include <cuda_runtime.h>

// YOLOv1 loss, fused single pass, issue-optimized.
// pred/target: [4096, 7, 7, 90] float32 contiguous. Output: scalar float32.
//
// Each warp owns 64 contiguous cells, processed as 2 batches of 32.
// Phase 1 (per cell): coalesced loads, per-lane weighted class-loss
//   accumulation (no warp reduce; only 1 shfl for conf_t), no-obj conf loss
//   folded into lanes 4/9, box floats (10 pred + 10 target) staged to smem.
// Phase 2 (per batch): lane i does the complete box/IoU/select math for
//   cell i of the batch -> 32 cells in parallel, zero divergence.
// Single warp-reduce + block-reduce + atomicAdd at the very end.

#define NFEAT 90
#define NCELLS (4096 * 7 * 7)      // 200704
#define INV_BATCH (1.0f / 4096.0f)
#define WARPS_PER_BLOCK 8
#define NBLOCKS 392                 // 392*8 warps * 64 cells = 200704

__global__ void yolo_zero_kernel(float* out) {
    if (threadIdx.x == 0) out[0] = 0.0f;
}

__global__ __launch_bounds__(256) void yolo_loss_kernel(
    const float* __restrict__ pred,
    const float* __restrict__ target,
    float* __restrict__ out)
{
    const float inv_s = 1.0f / 7.0f;
    const unsigned FULL = 0xffffffffu;

    const int lane   = threadIdx.x & 31;
    const int wid    = threadIdx.x >> 5;           // warp in block
    const int warp_g = blockIdx.x * WARPS_PER_BLOCK + wid;

    // Staging: [warp][cell-in-batch][20 floats + 1 pad] -> stride 21 is
    // coprime with 32 banks => conflict-free in both store and load phases.
    __shared__ float sbuf[WARPS_PER_BLOCK][32][21];

    float acc = 0.0f;

    #pragma unroll
    for (int b = 0; b < 2; b++) {
        const int cell0 = (warp_g * 2 + b) * 32;

        // ---------------- Phase 1: stream 32 cells ----------------
        #pragma unroll 4
        for (int ci = 0; ci < 32; ci++) {
            const float* p = pred   + (size_t)(cell0 + ci) * NFEAT;
            const float* t = target + (size_t)(cell0 + ci) * NFEAT;

            float p0 = p[lane];
            float t0 = t[lane];
            float p1 = p[lane + 32];
            float t1 = t[lane + 32];
            float p2 = 0.0f, t2 = 0.0f;
            if (lane < 26) { p2 = p[lane + 64]; t2 = t[lane + 64]; }

            // broadcast target confidence (element 4) to all lanes
            float conf_t = __shfl_sync(FULL, t0, 4);
            float coord_m = (conf_t > 0.0f) ? 1.0f : 0.0f;

            // class-loss partial for this lane (indices 10..89)
            float d0 = p0 - t0;
            float d1 = p1 - t1;
            float d2 = p2 - t2;
            float cls = d1 * d1 + d2 * d2;
            if (lane >= 10) cls += d0 * d0;
            acc += coord_m * cls;

            // no-object confidence loss: elements 4 and 9, weight 0.5
            if ((lane == 4 || lane == 9) && conf_t == 0.0f)
                acc += 0.5f * d0 * d0;

            // stage the 10 box/conf floats of each tensor
            if (lane < 10) {
                sbuf[wid][ci][lane]      = p0;
                sbuf[wid][ci][lane + 10] = t0;
            }
        }
        __syncwarp();

        // ---------------- Phase 2: box math, one cell per lane ----------------
        {
            const float* s = sbuf[wid][lane];
            float pp0 = s[0],  pp1 = s[1],  pp2 = s[2],  pp3 = s[3],  pp4 = s[4];
            float pp5 = s[5],  pp6 = s[6],  pp7 = s[7],  pp8 = s[8],  pp9 = s[9];
            float tt0 = s[10], tt1 = s[11], tt2 = s[12], tt3 = s[13], tt4 = s[14];
            float tt5 = s[15], tt6 = s[16], tt7 = s[17], tt8 = s[18];

            float coord_m = (tt4 > 0.0f) ? 1.0f : 0.0f;

            // pred box 0
            float pax0 = pp0 * inv_s - 0.5f * pp2;
            float pay0 = pp1 * inv_s - 0.5f * pp3;
            float pbx0 = pax0 * inv_s + 0.5f * pp2;
            float pby0 = pay0 * inv_s + 0.5f * pp3;
            // pred box 1
            float pax1 = pp5 * inv_s - 0.5f * pp7;
            float pay1 = pp6 * inv_s - 0.5f * pp8;
            float pbx1 = pax1 * inv_s + 0.5f * pp7;
            float pby1 = pay1 * inv_s + 0.5f * pp8;

            // target box 0
            float tax = tt0 * inv_s - 0.5f * tt2;
            float tay = tt1 * inv_s - 0.5f * tt3;
            float tbx = tax * inv_s + 0.5f * tt2;
            float tby = tay * inv_s + 0.5f * tt3;
            float t_area = (tbx - tax) * (tby - tay);

            // IoU box 0
            float w0 = fmaxf(fminf(pbx0, tbx) - fmaxf(pax0, tax), 0.0f);
            float h0 = fmaxf(fminf(pby0, tby) - fmaxf(pay0, tay), 0.0f);
            float inter0 = w0 * h0;
            float parea0 = (pbx0 - pax0) * (pby0 - pay0);
            float iou0 = inter0 / (parea0 + t_area - inter0);
            // IoU box 1
            float w1 = fmaxf(fminf(pbx1, tbx) - fmaxf(pax1, tax), 0.0f);
            float h1 = fmaxf(fminf(pby1, tby) - fmaxf(pay1, tay), 0.0f);
            float inter1 = w1 * h1;
            float parea1 = (pbx1 - pax1) * (pby1 - pay1);
            float iou1 = inter1 / (parea1 + t_area - inter1);

            // argmax (strict > matches jnp.argmax first-max semantics)
            bool sel1 = (iou1 > iou0);
            float max_iou = sel1 ? iou1 : iou0;

            float psx = sel1 ? pax1 : pax0;
            float psy = sel1 ? pay1 : pay0;
            float psw = sel1 ? pbx1 : pbx0;
            float psh = sel1 ? pby1 : pby0;
            float psc = sel1 ? pp9  : pp4;

            // tsel: transformed first target box if idx==0, raw box 1 otherwise
            float tsx = sel1 ? tt5 : tax;
            float tsy = sel1 ? tt6 : tay;
            float tsw = sel1 ? tt7 : tbx;
            float tsh = sel1 ? tt8 : tby;

            float dx = psx - tsx, dy = psy - tsy;
            float dw = psw - tsw, dh = psh - tsh;
            float xy_wh = dx * dx + dy * dy + dw * dw + dh * dh;
            float dc = psc - max_iou;

            acc += coord_m * (5.0f * xy_wh + dc * dc);
        }
        __syncwarp();   // before next batch overwrites sbuf
    }

    // ---------------- final reduction ----------------
    #pragma unroll
    for (int o = 16; o > 0; o >>= 1)
        acc += __shfl_xor_sync(FULL, acc, o);

    __shared__ float smem[WARPS_PER_BLOCK];
    if (lane == 0) smem[wid] = acc;
    __syncthreads();
    if (threadIdx.x == 0) {
        float tot = 0.0f;
        #pragma unroll
        for (int i = 0; i < WARPS_PER_BLOCK; i++) tot += smem[i];
        atomicAdd(out, tot * INV_BATCH);
    }
}

extern "C" void kernel_launch(void* const* d_in, const int* in_sizes, int n_in,
                              void* d_out, int out_size) {
    const float* pred   = (const float*)d_in[0];
    const float* target = (const float*)d_in[1];
    float* out = (float*)d_out;
    (void)in_sizes; (void)n_in; (void)out_size;

    yolo_zero_kernel<<<1, 32>>>(out);
    yolo_loss_kernel<<<NBLOCKS, 256>>>(pred, target, out);
}

// round 3
// speedup vs baseline: 1.8435x; 1.0867x over previous
#include <cuda_runtime.h>

// YOLOv1 loss, fused single pass, occupancy-optimized.
// pred/target: [4096, 7, 7, 90] float32 contiguous. Output: scalar float32.
//
// Each warp owns exactly 32 contiguous cells (one batch).
// Phase 1 (per cell): coalesced loads, per-lane weighted class-loss
//   accumulation (1 shfl for conf_t), no-obj conf loss in lanes 4/9,
//   box floats (10 pred + 10 target) staged to smem.
// Phase 2: lane i does the complete box/IoU/select math for cell i.
// Warp-reduce + block-reduce + atomicAdd at the end.
//
// Grid: 784 blocks x 8 warps x 32 cells = 200704 cells, all blocks
// resident in one wave (capacity 1184 @ 256 thr/block on 148 SMs).

#define NFEAT 90
#define NCELLS (4096 * 7 * 7)      // 200704
#define INV_BATCH (1.0f / 4096.0f)
#define WARPS_PER_BLOCK 8
#define NBLOCKS 784                 // 784*8 warps * 32 cells = 200704

__global__ void yolo_zero_kernel(float* out) {
    if (threadIdx.x == 0) out[0] = 0.0f;
}

__global__ __launch_bounds__(256) void yolo_loss_kernel(
    const float* __restrict__ pred,
    const float* __restrict__ target,
    float* __restrict__ out)
{
    const float inv_s = 1.0f / 7.0f;
    const unsigned FULL = 0xffffffffu;

    const int lane   = threadIdx.x & 31;
    const int wid    = threadIdx.x >> 5;
    const int warp_g = blockIdx.x * WARPS_PER_BLOCK + wid;

    // [warp][cell][20 floats + 1 pad] -> stride 21 coprime with 32 banks.
    __shared__ float sbuf[WARPS_PER_BLOCK][32][21];

    float acc = 0.0f;

    const int cell0 = warp_g * 32;

    // ---------------- Phase 1: stream 32 cells ----------------
    #pragma unroll 4
    for (int ci = 0; ci < 32; ci++) {
        const float* p = pred   + (size_t)(cell0 + ci) * NFEAT;
        const float* t = target + (size_t)(cell0 + ci) * NFEAT;

        float p0 = p[lane];
        float t0 = t[lane];
        float p1 = p[lane + 32];
        float t1 = t[lane + 32];
        float p2 = 0.0f, t2 = 0.0f;
        if (lane < 26) { p2 = p[lane + 64]; t2 = t[lane + 64]; }

        // broadcast target confidence (element 4)
        float conf_t = __shfl_sync(FULL, t0, 4);
        float coord_m = (conf_t > 0.0f) ? 1.0f : 0.0f;

        // class-loss partial (indices 10..89)
        float d0 = p0 - t0;
        float d1 = p1 - t1;
        float d2 = p2 - t2;
        float cls = d1 * d1 + d2 * d2;
        if (lane >= 10) cls += d0 * d0;
        acc += coord_m * cls;

        // no-object confidence loss (elements 4, 9), weight 0.5
        if ((lane == 4 || lane == 9) && conf_t == 0.0f)
            acc += 0.5f * d0 * d0;

        // stage box/conf floats
        if (lane < 10) {
            sbuf[wid][ci][lane]      = p0;
            sbuf[wid][ci][lane + 10] = t0;
        }
    }
    __syncwarp();

    // ---------------- Phase 2: box math, one cell per lane ----------------
    {
        const float* s = sbuf[wid][lane];
        float pp0 = s[0],  pp1 = s[1],  pp2 = s[2],  pp3 = s[3],  pp4 = s[4];
        float pp5 = s[5],  pp6 = s[6],  pp7 = s[7],  pp8 = s[8],  pp9 = s[9];
        float tt0 = s[10], tt1 = s[11], tt2 = s[12], tt3 = s[13], tt4 = s[14];
        float tt5 = s[15], tt6 = s[16], tt7 = s[17], tt8 = s[18];

        float coord_m = (tt4 > 0.0f) ? 1.0f : 0.0f;

        // pred box 0
        float pax0 = pp0 * inv_s - 0.5f * pp2;
        float pay0 = pp1 * inv_s - 0.5f * pp3;
        float pbx0 = pax0 * inv_s + 0.5f * pp2;
        float pby0 = pay0 * inv_s + 0.5f * pp3;
        // pred box 1
        float pax1 = pp5 * inv_s - 0.5f * pp7;
        float pay1 = pp6 * inv_s - 0.5f * pp8;
        float pbx1 = pax1 * inv_s + 0.5f * pp7;
        float pby1 = pay1 * inv_s + 0.5f * pp8;

        // target box 0
        float tax = tt0 * inv_s - 0.5f * tt2;
        float tay = tt1 * inv_s - 0.5f * tt3;
        float tbx = tax * inv_s + 0.5f * tt2;
        float tby = tay * inv_s + 0.5f * tt3;
        float t_area = (tbx - tax) * (tby - tay);

        // IoU box 0
        float w0 = fmaxf(fminf(pbx0, tbx) - fmaxf(pax0, tax), 0.0f);
        float h0 = fmaxf(fminf(pby0, tby) - fmaxf(pay0, tay), 0.0f);
        float inter0 = w0 * h0;
        float parea0 = (pbx0 - pax0) * (pby0 - pay0);
        float iou0 = inter0 / (parea0 + t_area - inter0);
        // IoU box 1
        float w1 = fmaxf(fminf(pbx1, tbx) - fmaxf(pax1, tax), 0.0f);
        float h1 = fmaxf(fminf(pby1, tby) - fmaxf(pay1, tay), 0.0f);
        float inter1 = w1 * h1;
        float parea1 = (pbx1 - pax1) * (pby1 - pay1);
        float iou1 = inter1 / (parea1 + t_area - inter1);

        // argmax (strict >)
        bool sel1 = (iou1 > iou0);
        float max_iou = sel1 ? iou1 : iou0;

        float psx = sel1 ? pax1 : pax0;
        float psy = sel1 ? pay1 : pay0;
        float psw = sel1 ? pbx1 : pbx0;
        float psh = sel1 ? pby1 : pby0;
        float psc = sel1 ? pp9  : pp4;

        float tsx = sel1 ? tt5 : tax;
        float tsy = sel1 ? tt6 : tay;
        float tsw = sel1 ? tt7 : tbx;
        float tsh = sel1 ? tt8 : tby;

        float dx = psx - tsx, dy = psy - tsy;
        float dw = psw - tsw, dh = psh - tsh;
        float xy_wh = dx * dx + dy * dy + dw * dw + dh * dh;
        float dc = psc - max_iou;

        acc += coord_m * (5.0f * xy_wh + dc * dc);
    }

    // ---------------- final reduction ----------------
    #pragma unroll
    for (int o = 16; o > 0; o >>= 1)
        acc += __shfl_xor_sync(FULL, acc, o);

    __shared__ float smem[WARPS_PER_BLOCK];
    if (lane == 0) smem[wid] = acc;
    __syncthreads();
    if (threadIdx.x == 0) {
        float tot = 0.0f;
        #pragma unroll
        for (int i = 0; i < WARPS_PER_BLOCK; i++) tot += smem[i];
        atomicAdd(out, tot * INV_BATCH);
    }
}

extern "C" void kernel_launch(void* const* d_in, const int* in_sizes, int n_in,
                              void* d_out, int out_size) {
    const float* pred   = (const float*)d_in[0];
    const float* target = (const float*)d_in[1];
    float* out = (float*)d_out;
    (void)in_sizes; (void)n_in; (void)out_size;

    yolo_zero_kernel<<<1, 32>>>(out);
    yolo_loss_kernel<<<NBLOCKS, 256>>>(pred, target, out);
}